// round 1
// baseline (speedup 1.0000x reference)
#include <cuda_runtime.h>
#include <cuda_bf16.h>
#include <cfloat>

#define G_BOXES 50
#define INF_V 100000000.0f
#define NUM_CLASSES 80

__global__ void assign_targets_kernel(
    const float* __restrict__ loc,       // [L,2]
    const float* __restrict__ stride,    // [L]
    const float* __restrict__ sr,        // [L,2]
    const float* __restrict__ boxes,     // [B,G,4]
    const int*   __restrict__ classes,   // [B,G]
    float* __restrict__ out,             // [6*B*L] = labels | reg | ctr
    int L, int B)
{
    __shared__ float sx1[G_BOXES], sy1[G_BOXES], sx2[G_BOXES], sy2[G_BOXES];
    __shared__ float scx[G_BOXES], scy[G_BOXES], sarea[G_BOXES];
    __shared__ int   scls[G_BOXES];

    const int b = blockIdx.y;
    const int t = threadIdx.x;

    if (t < G_BOXES) {
        const float* bx = boxes + (size_t)(b * G_BOXES + t) * 4;
        float x1 = bx[0], y1 = bx[1], x2 = bx[2], y2 = bx[3];
        sx1[t] = x1; sy1[t] = y1; sx2[t] = x2; sy2[t] = y2;
        scx[t] = (x1 + x2) * 0.5f;
        scy[t] = (y1 + y2) * 0.5f;
        sarea[t] = (x2 - x1) * (y2 - y1);
        scls[t] = classes[b * G_BOXES + t];
    }
    __syncthreads();

    const int i = blockIdx.x * blockDim.x + t;
    if (i >= L) return;

    const float x  = loc[2 * i];
    const float y  = loc[2 * i + 1];
    const float s  = stride[i];
    const float lo = sr[2 * i];
    const float hi = sr[2 * i + 1];
    const float rad = s * 1.5f;

    float best = FLT_MAX;   // > INF_V so g=0 always claims first (matches argmin first-min)
    int   bg   = 0;

    #pragma unroll 10
    for (int g = 0; g < G_BOXES; g++) {
        const float l  = x - sx1[g];
        const float tt = y - sy1[g];
        const float r  = sx2[g] - x;
        const float bb = sy2[g] - y;

        // center-sampling box intersection, simplified:
        // min over {x-x0, y-y0, x1-x, y1-y} with x0=max(cx-rad,x1) etc.
        //  = min( rad - max(|x-cx|,|y-cy|), min(l,t,r,b) )
        const float dx = fabsf(x - scx[g]);
        const float dy = fabsf(y - scy[g]);
        const float min_lr = fminf(l, r);
        const float min_tb = fminf(tt, bb);
        const float mincb  = fminf(rad - fmaxf(dx, dy), fminf(min_lr, min_tb));

        const float maxreg = fminf(fmaxf(l, r), fmaxf(tt, bb));

        const bool valid = (mincb > 0.0f) & (maxreg >= lo) & (maxreg <= hi);
        const float a = valid ? sarea[g] : INF_V;
        if (a < best) { best = a; bg = g; }
    }

    // gather winning box regression targets
    const float l  = (x - sx1[bg]) / s;
    const float tt = (y - sy1[bg]) / s;
    const float r  = (sx2[bg] - x) / s;
    const float bb = (sy2[bg] - y) / s;

    const int label = (best >= INF_V) ? NUM_CLASSES : scls[bg];

    // centerness
    const float rl = l + 1e-5f, rr = r + 1e-5f;
    const float rt = tt + 1e-5f, rb = bb + 1e-5f;
    float ctr = (fminf(rl, rr) / fmaxf(rl, rr)) * (fminf(rt, rb) / fmaxf(rt, rb));
    ctr = sqrtf(fmaxf(ctr, 0.0f));

    const size_t BL  = (size_t)B * L;
    const size_t idx = (size_t)b * L + i;

    out[idx] = (float)label;                         // labels
    float4* regv = (float4*)(out + BL);              // reg_t [B,L,4]
    regv[idx] = make_float4(l, tt, r, bb);
    out[5 * BL + idx] = ctr;                         // ctr
}

extern "C" void kernel_launch(void* const* d_in, const int* in_sizes, int n_in,
                              void* d_out, int out_size) {
    const float* loc     = (const float*)d_in[0];   // [L,2]
    const float* stride  = (const float*)d_in[1];   // [L]
    const float* sr      = (const float*)d_in[2];   // [L,2]
    const float* boxes   = (const float*)d_in[3];   // [B,G,4]
    const int*   classes = (const int*)d_in[4];     // [B,G]
    float* out = (float*)d_out;

    const int L = in_sizes[1];
    const int B = in_sizes[4] / G_BOXES;

    dim3 block(256);
    dim3 grid((L + 255) / 256, B);
    assign_targets_kernel<<<grid, block>>>(loc, stride, sr, boxes, classes, out, L, B);
}

// round 2
// speedup vs baseline: 1.1115x; 1.1115x over previous
#include <cuda_runtime.h>
#include <cuda_bf16.h>
#include <cfloat>

#define G_BOXES 50
#define INF_V 100000000.0f
#define NUM_CLASSES_F 80.0f

__global__ void __launch_bounds__(256, 4) assign_targets_kernel(
    const float* __restrict__ loc,       // [L,2]
    const float* __restrict__ stride,    // [L]
    const float* __restrict__ sr,        // [L,2]
    const float* __restrict__ boxes,     // [B,G,4]
    const int*   __restrict__ classes,   // [B,G]
    float* __restrict__ out,             // [6*B*L] = labels | reg | ctr
    int L, int B)
{
    __shared__ float4 sbox[G_BOXES];   // x1,y1,x2,y2
    __shared__ float4 saux[G_BOXES];   // cx,cy,area,cls(as float)

    const int b = blockIdx.y;
    const int t = threadIdx.x;

    if (t < G_BOXES) {
        float4 bx = ((const float4*)boxes)[b * G_BOXES + t];
        sbox[t] = bx;
        float cx = (bx.x + bx.z) * 0.5f;
        float cy = (bx.y + bx.w) * 0.5f;
        float area = (bx.z - bx.x) * (bx.w - bx.y);
        saux[t] = make_float4(cx, cy, area, (float)classes[b * G_BOXES + t]);
    }
    __syncthreads();

    // two locations per thread: i0 and i0+256 within a 512-wide block tile
    const int base = blockIdx.x * 512;
    const int i0 = base + t;
    const int i1 = base + 256 + t;
    const bool v0 = i0 < L;
    const bool v1 = i1 < L;
    const int c0 = v0 ? i0 : L - 1;
    const int c1 = v1 ? i1 : L - 1;

    const float2 xy0 = ((const float2*)loc)[c0];
    const float2 xy1 = ((const float2*)loc)[c1];
    const float2 sr0 = ((const float2*)sr)[c0];
    const float2 sr1 = ((const float2*)sr)[c1];
    const float  s0  = stride[c0];
    const float  s1  = stride[c1];
    const float  rad0 = s0 * 1.5f;
    const float  rad1 = s1 * 1.5f;

    float best0 = FLT_MAX, best1 = FLT_MAX;  // > INF_V: matches first-occurrence argmin
    int   bg0 = 0, bg1 = 0;

    #pragma unroll 10
    for (int g = 0; g < G_BOXES; g++) {
        const float4 bx = sbox[g];   // LDS.128 broadcast
        const float4 ax = saux[g];   // LDS.128 broadcast
        // ---- location 0 ----
        {
            const float l  = xy0.x - bx.x;
            const float tt = xy0.y - bx.y;
            const float r  = bx.z - xy0.x;
            const float bb = bx.w - xy0.y;
            const float dx = xy0.x - ax.x;
            const float dy = xy0.y - ax.y;
            const float maxd = fmaxf(fabsf(dx), fabsf(dy));
            const float m4   = fminf(fminf(l, r), fminf(tt, bb));
            const float mr   = fminf(fmaxf(l, r), fmaxf(tt, bb));
            const bool p = (maxd < rad0) & (m4 > 0.0f) &
                           (mr >= sr0.x) & (mr <= sr0.y) & (ax.z < best0);
            if (p) { best0 = ax.z; bg0 = g; }
        }
        // ---- location 1 ----
        {
            const float l  = xy1.x - bx.x;
            const float tt = xy1.y - bx.y;
            const float r  = bx.z - xy1.x;
            const float bb = bx.w - xy1.y;
            const float dx = xy1.x - ax.x;
            const float dy = xy1.y - ax.y;
            const float maxd = fmaxf(fabsf(dx), fabsf(dy));
            const float m4   = fminf(fminf(l, r), fminf(tt, bb));
            const float mr   = fminf(fmaxf(l, r), fmaxf(tt, bb));
            const bool p = (maxd < rad1) & (m4 > 0.0f) &
                           (mr >= sr1.x) & (mr <= sr1.y) & (ax.z < best1);
            if (p) { best1 = ax.z; bg1 = g; }
        }
    }

    const size_t BL = (size_t)B * L;

    // ---- epilogue for location 0 ----
    if (v0) {
        const float4 wb = sbox[bg0];
        const float4 wa = saux[bg0];
        const float l  = (xy0.x - wb.x) / s0;
        const float tt = (xy0.y - wb.y) / s0;
        const float r  = (wb.z - xy0.x) / s0;
        const float bb = (wb.w - xy0.y) / s0;
        const float label = (best0 >= INF_V) ? NUM_CLASSES_F : wa.w;
        const float rl = l + 1e-5f, rr = r + 1e-5f;
        const float rt = tt + 1e-5f, rb = bb + 1e-5f;
        float ctr = (fminf(rl, rr) / fmaxf(rl, rr)) * (fminf(rt, rb) / fmaxf(rt, rb));
        ctr = sqrtf(fmaxf(ctr, 0.0f));
        const size_t idx = (size_t)b * L + i0;
        out[idx] = label;
        ((float4*)(out + BL))[idx] = make_float4(l, tt, r, bb);
        out[5 * BL + idx] = ctr;
    }
    // ---- epilogue for location 1 ----
    if (v1) {
        const float4 wb = sbox[bg1];
        const float4 wa = saux[bg1];
        const float l  = (xy1.x - wb.x) / s1;
        const float tt = (xy1.y - wb.y) / s1;
        const float r  = (wb.z - xy1.x) / s1;
        const float bb = (wb.w - xy1.y) / s1;
        const float label = (best1 >= INF_V) ? NUM_CLASSES_F : wa.w;
        const float rl = l + 1e-5f, rr = r + 1e-5f;
        const float rt = tt + 1e-5f, rb = bb + 1e-5f;
        float ctr = (fminf(rl, rr) / fmaxf(rl, rr)) * (fminf(rt, rb) / fmaxf(rt, rb));
        ctr = sqrtf(fmaxf(ctr, 0.0f));
        const size_t idx = (size_t)b * L + i1;
        out[idx] = label;
        ((float4*)(out + BL))[idx] = make_float4(l, tt, r, bb);
        out[5 * BL + idx] = ctr;
    }
}

extern "C" void kernel_launch(void* const* d_in, const int* in_sizes, int n_in,
                              void* d_out, int out_size) {
    const float* loc     = (const float*)d_in[0];   // [L,2]
    const float* stride  = (const float*)d_in[1];   // [L]
    const float* sr      = (const float*)d_in[2];   // [L,2]
    const float* boxes   = (const float*)d_in[3];   // [B,G,4]
    const int*   classes = (const int*)d_in[4];     // [B,G]
    float* out = (float*)d_out;

    const int L = in_sizes[1];
    const int B = in_sizes[4] / G_BOXES;

    dim3 block(256);
    dim3 grid((L + 511) / 512, B);
    assign_targets_kernel<<<grid, block>>>(loc, stride, sr, boxes, classes, out, L, B);
}